// round 13
// baseline (speedup 1.0000x reference)
#include <cuda_runtime.h>
#include <cstdint>

// ---------------- configuration ----------------
#define THREADS   1024
#define NWARP     (THREADS / 32)        // 32
#define IPT       4                     // items per thread
#define TILE      (THREADS * IPT)       // 4096 elements per block
#define NEXP      64
#define MAXB      296
#define NSLOT     (IPT * NWARP)         // 128 (round,warp) slots
#define NCHUNK    16                    // chunks; NSLOT/NCHUNK = 8 slots each

// ---------------- scratch (static device globals) ----------------
__device__ unsigned int g_blockHist[NEXP * MAXB];
__device__ unsigned int g_count = 0;
__device__ unsigned int g_gen   = 0;

// sense-reversing grid barrier; resets g_count each use -> graph-replay safe
__device__ __forceinline__ void grid_barrier(int nblocks) {
    __syncthreads();
    if (threadIdx.x == 0) {
        __threadfence();
        unsigned gen = *((volatile unsigned int*)&g_gen);
        if (atomicAdd(&g_count, 1u) == (unsigned)(nblocks - 1)) {
            g_count = 0u;
            __threadfence();
            *((volatile unsigned int*)&g_gen) = gen + 1u;
        } else {
            while (*((volatile unsigned int*)&g_gen) == gen) __nanosleep(64);
            __threadfence();
        }
    }
    __syncthreads();
}

__device__ __forceinline__ unsigned int warp_incl_scan(unsigned int v) {
    int lane = threadIdx.x & 31;
#pragma unroll
    for (int d = 1; d < 32; d <<= 1) {
        unsigned int n = __shfl_up_sync(0xFFFFFFFFu, v, d);
        if (lane >= d) v += n;
    }
    return v;
}

__global__ void __launch_bounds__(THREADS, 1)
fused_kernel(const float* __restrict__ scores,
             const int*   __restrict__ experts,
             const int*   __restrict__ topk_ptr,
             float* __restrict__ out_scores,
             float* __restrict__ out_tok,
             float* __restrict__ out_counts,
             int total, int B) {
    // all counts/prefixes are <= TILE=4096 -> fit in u16.
    // cnt16+sums16 (18 KB) are DEAD after placements are registered;
    // s_sc (16 KB) aliases over them.  Total static smem ~= 35 KB.
    __shared__ uint16_t     cnt16 [NSLOT * NEXP];   // 16 KB
    __shared__ uint16_t     sums16[NCHUNK * NEXP];  // 2 KB
    __shared__ unsigned int s_pk  [TILE];           // 16 KB: (e<<12)|j_orig
    __shared__ unsigned int tot_l [NEXP];
    __shared__ unsigned int ebl   [NEXP];           // block-local expert base
    __shared__ unsigned int sh_off[NEXP];           // global base of block's run
    __shared__ unsigned int s_pre [NEXP];
    __shared__ unsigned int s_w[2];
    float* s_sc = (float*)cnt16;                    // alias (after sync)

    const int t    = threadIdx.x;
    const int lane = t & 31;
    const int wid  = t >> 5;
    const int b    = blockIdx.x;

    const int topk  = *topk_ptr;
    const bool pow2 = (topk & (topk - 1)) == 0;
    const int shift = pow2 ? (31 - __clz(topk)) : 0;

    // zero count matrix (u32-wide)
#pragma unroll
    for (int i = t; i < NSLOT * NEXP / 2; i += THREADS)
        ((unsigned int*)cnt16)[i] = 0u;
    __syncthreads();

    // ---------------- Phase A: load experts+scores, warp ranks, counts ----
    const int base = b * TILE;
    int   e[IPT];
    int   rk[IPT];
    float sc[IPT];

#pragma unroll
    for (int r = 0; r < IPT; r++) {
        int idx = base + r * THREADS + t;            // striped = flat order
        bool ok = idx < total;
        e[r]  = ok ? experts[idx] : -1;
        sc[r] = ok ? scores[idx] : 0.0f;             // coalesced, overlapped
        unsigned int mask = __match_any_sync(0xFFFFFFFFu, e[r]);
        rk[r] = __popc(mask & ((1u << lane) - 1u));
        if (lane == (__ffs(mask) - 1) && (unsigned)e[r] < NEXP)
            cnt16[(r * NWARP + wid) * NEXP + e[r]] = (uint16_t)__popc(mask);
    }
    __syncthreads();

    // chunk sums over slots per expert
    {
        int c = t >> 6, ee = t & 63;
        unsigned int s = 0;
#pragma unroll
        for (int i = 0; i < NSLOT / NCHUNK; i++)
            s += cnt16[(c * (NSLOT / NCHUNK) + i) * NEXP + ee];
        sums16[c * NEXP + ee] = (uint16_t)s;
    }
    __syncthreads();
    // scan chunk sums per expert -> block histogram
    if (t < NEXP) {
        unsigned int run = 0;
#pragma unroll
        for (int c = 0; c < NCHUNK; c++) {
            unsigned int v = sums16[c * NEXP + t];
            sums16[c * NEXP + t] = (uint16_t)run;
            run += v;
        }
        g_blockHist[t * B + b] = run;                // expert-major
        tot_l[t] = run;
    }
    __syncthreads();
    // rewrite cnt with within-expert exclusive prefixes
    {
        int c = t >> 6, ee = t & 63;
        unsigned int run = sums16[c * NEXP + ee];
#pragma unroll
        for (int i = 0; i < NSLOT / NCHUNK; i++) {
            int k = c * (NSLOT / NCHUNK) + i;
            unsigned int v = cnt16[k * NEXP + ee];
            cnt16[k * NEXP + ee] = (uint16_t)run;
            run += v;
        }
    }
    // block-local expert bases (exclusive scan over 64 totals, 2 warps)
    unsigned int vv = 0, inc = 0;
    if (t < NEXP) {
        vv = tot_l[t];
        inc = warp_incl_scan(vv);
        if (t == 31) s_w[0] = inc;
    }
    __syncthreads();
    if (t < NEXP) ebl[t] = inc - vv + ((t >= 32) ? s_w[0] : 0u);
    __syncthreads();

    // placements into registers (last use of cnt16 as counts)
    unsigned int pl[IPT];
#pragma unroll
    for (int r = 0; r < IPT; r++) {
        pl[r] = 0xFFFFFFFFu;
        if ((unsigned)e[r] < NEXP) {
            int jo = r * THREADS + t;
            pl[r] = ebl[e[r]]
                  + cnt16[(r * NWARP + wid) * NEXP + e[r]]
                  + (unsigned int)rk[r];
            s_pk[pl[r]] = ((unsigned int)e[r] << 12) | (unsigned int)jo;
        }
    }
    __syncthreads();    // cnt16 reads done -> safe to overwrite with s_sc

    // stage scores in sorted order (aliases cnt16/sums16)
#pragma unroll
    for (int r = 0; r < IPT; r++)
        if (pl[r] != 0xFFFFFFFFu) s_sc[pl[r]] = sc[r];

    grid_barrier(B);

    // ---------------- Phase C: global bases from full hist matrix ---------
    // 16 threads per expert: ee = t>>4, sub = t&15
    {
        int ee = t >> 4, sub = t & 15;
        unsigned int tot = 0, pre = 0;
        for (int b2 = sub; b2 < B; b2 += 16) {
            unsigned int v = g_blockHist[ee * B + b2];
            tot += v;
            if (b2 < b) pre += v;
        }
#pragma unroll
        for (int d = 1; d < 16; d <<= 1) {
            tot += __shfl_xor_sync(0xFFFFFFFFu, tot, d);
            pre += __shfl_xor_sync(0xFFFFFFFFu, pre, d);
        }
        if (sub == 0) { tot_l[ee] = tot; s_pre[ee] = pre; }
    }
    __syncthreads();
    unsigned int tv = 0, ti = 0;
    if (t < NEXP) {
        tv = tot_l[t];
        ti = warp_incl_scan(tv);
        if (t == 31) s_w[1] = ti;
    }
    __syncthreads();
    if (t < NEXP) {
        unsigned int ebase = ti - tv + ((t >= 32) ? s_w[1] : 0u);
        sh_off[t] = ebase + s_pre[t];
        if (b == 0) out_counts[t] = (float)tv;
    }
    __syncthreads();

    // ---------------- write-out: smem only -> fully coalesced stores ------
    const int valid = min(TILE, total - base);
#pragma unroll
    for (int r = 0; r < IPT; r++) {
        int j = r * THREADS + t;                     // sorted position
        if (j < valid) {
            unsigned int pk = s_pk[j];
            unsigned int ee = pk >> 12;
            int jo  = (int)(pk & 0x0FFFu);
            int idx = base + jo;
            unsigned int dst = sh_off[ee] + (unsigned int)j - ebl[ee];
            int tok = pow2 ? (idx >> shift) : (idx / topk);
            out_scores[dst] = s_sc[j];
            out_tok[dst]    = (float)tok;
        }
    }
}

// ---------------- launch ----------------
extern "C" void kernel_launch(void* const* d_in, const int* in_sizes, int n_in,
                              void* d_out, int out_size) {
    const float* scores   = (const float*)d_in[0];
    const int*   experts  = (const int*)  d_in[1];
    const int*   topk_ptr = (const int*)  d_in[3];

    int total = in_sizes[0];                        // 524288
    int B = (total + TILE - 1) / TILE;              // 128
    if (B > MAXB) B = MAXB;                         // all blocks co-resident

    float* out        = (float*)d_out;
    float* out_scores = out;                        // [0, total)
    float* out_tok    = out + total;                // [total, 2*total)
    float* out_counts = out + 2 * (size_t)total;    // [2*total, +64)

    fused_kernel<<<B, THREADS>>>(scores, experts, topk_ptr,
                                 out_scores, out_tok, out_counts,
                                 total, B);
}